// round 1
// baseline (speedup 1.0000x reference)
#include <cuda_runtime.h>
#include <math.h>

// ---------------------------------------------------------------------------
// Problem constants: B=2, L=2048, D=2048, H=16, dk=64, dv=128
// M = B*L = 4096 tokens.
// ---------------------------------------------------------------------------
#define MTOK 4096
#define DMODEL 2048
#define DQK 1024
#define NHEAD 16
#define DK 64
#define DV 128
#define SEQ 2048
#define SCALE_K 0.08838834764831845f   // 128^-0.5
#define INV_NORM 0.0625f               // 1/16

// Scratch (device globals: no allocation allowed)
__device__ float g_q [MTOK * DQK];
__device__ float g_k [MTOK * DQK];
__device__ float g_kg[MTOK * DQK];
__device__ float g_v [MTOK * DMODEL];
__device__ float g_gp[MTOK * DMODEL];
__device__ float g_o [MTOK * DMODEL];
__device__ float g_t16[MTOK * 16];

// ---------------------------------------------------------------------------
// Tiled SGEMM:  C[M,N] = alpha * A[M,K] @ B[N,K]^T (+ bias[N])
// 128x128 block tile, BK=16, 256 threads, 8x8 per-thread micro-tile.
// Assumes M,N % 128 == 0, K % 16 == 0 (true for all calls here).
// ---------------------------------------------------------------------------
__global__ __launch_bounds__(256)
void sgemm_nt(const float* __restrict__ A, const float* __restrict__ B,
              const float* __restrict__ bias, float* __restrict__ C,
              int M, int N, int K, float alpha)
{
    __shared__ __align__(16) float As[16][132];
    __shared__ __align__(16) float Bs[16][132];

    const int tid = threadIdx.x;
    const int bm  = blockIdx.y * 128;
    const int bn  = blockIdx.x * 128;

    const int lr = tid >> 2;          // 0..63  (load row)
    const int lc = (tid & 3) << 2;    // 0,4,8,12 (load col, float4)
    const int tr = tid >> 4;          // 0..15 (compute tile row)
    const int tc = tid & 15;          // 0..15 (compute tile col)

    float acc[8][8];
#pragma unroll
    for (int i = 0; i < 8; i++)
#pragma unroll
        for (int j = 0; j < 8; j++) acc[i][j] = 0.f;

    const float* Ap0 = A + (size_t)(bm + lr) * K + lc;
    const float* Ap1 = Ap0 + (size_t)64 * K;
    const float* Bp0 = B + (size_t)(bn + lr) * K + lc;
    const float* Bp1 = Bp0 + (size_t)64 * K;

    for (int k0 = 0; k0 < K; k0 += 16) {
        float4 a0 = *(const float4*)(Ap0 + k0);
        float4 a1 = *(const float4*)(Ap1 + k0);
        float4 b0 = *(const float4*)(Bp0 + k0);
        float4 b1 = *(const float4*)(Bp1 + k0);

        As[lc + 0][lr]      = a0.x; As[lc + 1][lr]      = a0.y;
        As[lc + 2][lr]      = a0.z; As[lc + 3][lr]      = a0.w;
        As[lc + 0][lr + 64] = a1.x; As[lc + 1][lr + 64] = a1.y;
        As[lc + 2][lr + 64] = a1.z; As[lc + 3][lr + 64] = a1.w;
        Bs[lc + 0][lr]      = b0.x; Bs[lc + 1][lr]      = b0.y;
        Bs[lc + 2][lr]      = b0.z; Bs[lc + 3][lr]      = b0.w;
        Bs[lc + 0][lr + 64] = b1.x; Bs[lc + 1][lr + 64] = b1.y;
        Bs[lc + 2][lr + 64] = b1.z; Bs[lc + 3][lr + 64] = b1.w;
        __syncthreads();

#pragma unroll
        for (int kk = 0; kk < 16; kk++) {
            float4 av0 = *(const float4*)&As[kk][tr * 8];
            float4 av1 = *(const float4*)&As[kk][tr * 8 + 4];
            float4 bv0 = *(const float4*)&Bs[kk][tc * 8];
            float4 bv1 = *(const float4*)&Bs[kk][tc * 8 + 4];
            float a[8] = {av0.x, av0.y, av0.z, av0.w, av1.x, av1.y, av1.z, av1.w};
            float b[8] = {bv0.x, bv0.y, bv0.z, bv0.w, bv1.x, bv1.y, bv1.z, bv1.w};
#pragma unroll
            for (int i = 0; i < 8; i++)
#pragma unroll
                for (int j = 0; j < 8; j++)
                    acc[i][j] = fmaf(a[i], b[j], acc[i][j]);
        }
        __syncthreads();
    }

#pragma unroll
    for (int i = 0; i < 8; i++) {
        int row = bm + tr * 8 + i;
        float* Cr = C + (size_t)row * N + bn + tc * 8;
        if (bias) {
            const float* br = bias + bn + tc * 8;
#pragma unroll
            for (int j = 0; j < 8; j++) Cr[j] = acc[i][j] * alpha + br[j];
        } else {
#pragma unroll
            for (int j = 0; j < 8; j++) Cr[j] = acc[i][j] * alpha;
        }
    }
}

// ---------------------------------------------------------------------------
// Low-rank gate stage 1: t16[m][n] = x[m,:] . Wkg1[n,:]   (n < 16, K=2048)
// ---------------------------------------------------------------------------
__global__ void kg_gemm1(const float* __restrict__ x, const float* __restrict__ W,
                         float* __restrict__ t16)
{
    int idx = blockIdx.x * blockDim.x + threadIdx.x;   // 4096*16
    int m = idx >> 4, n = idx & 15;
    const float* xr = x + (size_t)m * DMODEL;
    const float* wr = W + (size_t)n * DMODEL;
    float acc = 0.f;
#pragma unroll 4
    for (int kk = 0; kk < DMODEL; kk += 4) {
        float4 a = *(const float4*)(xr + kk);
        float4 b = *(const float4*)(wr + kk);
        acc += a.x * b.x + a.y * b.y + a.z * b.z + a.w * b.w;
    }
    t16[idx] = acc;
}

// Stage 2: kg[m][n] = t16[m,:16] . Wkg2[n,:16] + bkg2[n]
__global__ void kg_gemm2(const float* __restrict__ t16, const float* __restrict__ W2,
                         const float* __restrict__ b2, float* __restrict__ kg)
{
    int idx = blockIdx.x * blockDim.x + threadIdx.x;   // 4096*1024
    int m = idx >> 10, n = idx & 1023;
    const float* tr = t16 + (size_t)m * 16;
    const float* wr = W2 + (size_t)n * 16;
    float acc = b2[n];
#pragma unroll
    for (int c = 0; c < 16; c++) acc = fmaf(tr[c], wr[c], acc);
    kg[idx] = acc;
}

// ---------------------------------------------------------------------------
// GLA recurrence. One block per (b, head, dv-chunk of 32). 256 threads.
// Thread (j = tid/8 local v-col, ig = tid%8 owning 8 S-rows).
// Stages 16 timesteps of q/k/gate/v through SMEM per load phase.
//   S_t = S_{t-1} * exp(log_sigmoid(kg_t)/16) + k_t v_t^T ; o_t = q_t S_t
// ---------------------------------------------------------------------------
#define TT 16
__global__ __launch_bounds__(256)
void gla_rec(const float* __restrict__ q, const float* __restrict__ k,
             const float* __restrict__ kg, const float* __restrict__ v,
             float* __restrict__ o)
{
    const int blk   = blockIdx.x;       // 128 = B * H * 4
    const int chunk = blk & 3;
    const int head  = (blk >> 2) & 15;
    const int b     = blk >> 6;
    const int j0    = chunk * 32;

    const int tid = threadIdx.x;
    const int j   = tid >> 3;           // 0..31
    const int ig  = tid & 7;            // 0..7

    __shared__ float qs[TT][DK];
    __shared__ float ks[TT][DK];
    __shared__ float es[TT][DK];
    __shared__ float vs[TT][32];

    const float* qb = q  + (size_t)b * SEQ * DQK    + head * DK;
    const float* kb = k  + (size_t)b * SEQ * DQK    + head * DK;
    const float* gb = kg + (size_t)b * SEQ * DQK    + head * DK;
    const float* vb = v  + (size_t)b * SEQ * DMODEL + head * DV + j0;
    float*       ob = o  + (size_t)b * SEQ * DMODEL + head * DV + j0;

    float S[8] = {0.f, 0.f, 0.f, 0.f, 0.f, 0.f, 0.f, 0.f};

    for (int t0 = 0; t0 < SEQ; t0 += TT) {
        // load stage: q/k/gate (TT*64 each) + v (TT*32)
        for (int idx = tid; idx < TT * DK; idx += 256) {
            int tt = idx >> 6, i = idx & 63;
            size_t off = (size_t)(t0 + tt) * DQK + i;
            qs[tt][i] = qb[off];
            ks[tt][i] = kb[off];
            float xg = gb[off];
            float ls = (xg >= 0.f) ? -log1pf(expf(-xg)) : (xg - log1pf(expf(xg)));
            es[tt][i] = expf(ls * INV_NORM);
        }
        for (int idx = tid; idx < TT * 32; idx += 256) {
            int tt = idx >> 5, jj = idx & 31;
            vs[tt][jj] = vb[(size_t)(t0 + tt) * DMODEL + jj];
        }
        __syncthreads();

        for (int tt = 0; tt < TT; tt++) {
            float vj  = vs[tt][j];
            float acc = 0.f;
#pragma unroll
            for (int r = 0; r < 8; r++) {
                int i = ig * 8 + r;
                float s = fmaf(S[r], es[tt][i], ks[tt][i] * vj);
                S[r] = s;
                acc = fmaf(qs[tt][i], s, acc);
            }
            acc += __shfl_xor_sync(0xffffffffu, acc, 4);
            acc += __shfl_xor_sync(0xffffffffu, acc, 2);
            acc += __shfl_xor_sync(0xffffffffu, acc, 1);
            if (ig == 0) ob[(size_t)(t0 + tt) * DMODEL + j] = acc;
        }
        __syncthreads();
    }
}

// ---------------------------------------------------------------------------
// LayerNorm over dv=128 (no affine) + SiLU(gproj) gating.
// One warp per (b,l,h) row of 128; lane handles a float4.
// ---------------------------------------------------------------------------
__global__ __launch_bounds__(256)
void ln_gate(const float* __restrict__ o, const float* __restrict__ gp,
             float* __restrict__ z)
{
    int gw   = (blockIdx.x * blockDim.x + threadIdx.x) >> 5;   // row id, 65536 total
    int lane = threadIdx.x & 31;

    float4 ov = ((const float4*)(o + (size_t)gw * 128))[lane];
    float s = ov.x + ov.y + ov.z + ov.w;
#pragma unroll
    for (int d = 16; d > 0; d >>= 1) s += __shfl_xor_sync(0xffffffffu, s, d);
    float mu = s * (1.f / 128.f);

    float dx0 = ov.x - mu, dx1 = ov.y - mu, dx2 = ov.z - mu, dx3 = ov.w - mu;
    float vsum = dx0 * dx0 + dx1 * dx1 + dx2 * dx2 + dx3 * dx3;
#pragma unroll
    for (int d = 16; d > 0; d >>= 1) vsum += __shfl_xor_sync(0xffffffffu, vsum, d);
    float inv = rsqrtf(vsum * (1.f / 128.f) + 1e-5f);

    float4 gv = ((const float4*)(gp + (size_t)gw * 128))[lane];
    float4 zo;
    zo.x = (gv.x / (1.f + expf(-gv.x))) * (dx0 * inv);
    zo.y = (gv.y / (1.f + expf(-gv.y))) * (dx1 * inv);
    zo.z = (gv.z / (1.f + expf(-gv.z))) * (dx2 * inv);
    zo.w = (gv.w / (1.f + expf(-gv.w))) * (dx3 * inv);
    ((float4*)(z + (size_t)gw * 128))[lane] = zo;
}

// ---------------------------------------------------------------------------
extern "C" void kernel_launch(void* const* d_in, const int* in_sizes, int n_in,
                              void* d_out, int out_size)
{
    const float* x    = (const float*)d_in[0];
    const float* Wq   = (const float*)d_in[1];
    const float* Wk   = (const float*)d_in[2];
    const float* Wkg1 = (const float*)d_in[3];
    const float* Wkg2 = (const float*)d_in[4];
    const float* bkg2 = (const float*)d_in[5];
    const float* Wv   = (const float*)d_in[6];
    const float* Wg   = (const float*)d_in[7];
    const float* bg   = (const float*)d_in[8];
    const float* Wo   = (const float*)d_in[9];
    float* out = (float*)d_out;

    float *q, *k, *kg, *v, *gp, *o, *t16;
    cudaGetSymbolAddress((void**)&q,   g_q);
    cudaGetSymbolAddress((void**)&k,   g_k);
    cudaGetSymbolAddress((void**)&kg,  g_kg);
    cudaGetSymbolAddress((void**)&v,   g_v);
    cudaGetSymbolAddress((void**)&gp,  g_gp);
    cudaGetSymbolAddress((void**)&o,   g_o);
    cudaGetSymbolAddress((void**)&t16, g_t16);

    dim3 blk(256);
    dim3 gQK(DQK / 128, MTOK / 128);      // 8 x 32
    dim3 gD (DMODEL / 128, MTOK / 128);   // 16 x 32

    sgemm_nt<<<gQK, blk>>>(x, Wq, nullptr, q, MTOK, DQK, DMODEL, 1.f);
    sgemm_nt<<<gQK, blk>>>(x, Wk, nullptr, k, MTOK, DQK, DMODEL, SCALE_K);
    sgemm_nt<<<gD,  blk>>>(x, Wv, nullptr, v, MTOK, DMODEL, DMODEL, 1.f);
    sgemm_nt<<<gD,  blk>>>(x, Wg, bg,      gp, MTOK, DMODEL, DMODEL, 1.f);

    kg_gemm1<<<(MTOK * 16) / 256, 256>>>(x, Wkg1, t16);
    kg_gemm2<<<(MTOK * DQK) / 256, 256>>>(t16, Wkg2, bkg2, kg);

    gla_rec<<<128, 256>>>(q, k, kg, v, o);

    // z overwrites v (v fully consumed by the recurrence)
    ln_gate<<<(MTOK * NHEAD * 32) / 256, 256>>>(o, gp, v);

    sgemm_nt<<<gD, blk>>>(v, Wo, nullptr, out, MTOK, DMODEL, DMODEL, 1.f);
}

// round 4
// speedup vs baseline: 3.2871x; 3.2871x over previous
#include <cuda_runtime.h>
#include <cuda_bf16.h>
#include <math.h>
#include <cstdint>

// ---------------------------------------------------------------------------
// Problem constants: B=2, L=2048, D=2048, H=16, dk=64, dv=128.  M = B*L = 4096.
// ---------------------------------------------------------------------------
#define MTOK 4096
#define DMODEL 2048
#define DQK 1024
#define NHEAD 16
#define DK 64
#define DV 128
#define SEQ 2048
#define SCALE_K 0.08838834764831845f   // 128^-0.5
#define INV_NORM 0.0625f               // 1/16

// tcgen05 only exists in the arch-specific (sm_103a) compilation pass.
#if defined(__CUDA_ARCH__) && (__CUDA_ARCH__ == 1030) && defined(__CUDA_ARCH_FEAT_SM103_ALL)
#define USE_TCGEN05 1
#else
#define USE_TCGEN05 0
#endif

// ---------------------------------------------------------------------------
// Scratch (device globals: no allocation allowed)
// ---------------------------------------------------------------------------
__device__ float g_q [MTOK * DQK];
__device__ float g_k [MTOK * DQK];
__device__ float g_kg[MTOK * DQK];
__device__ float g_v [MTOK * DMODEL];
__device__ float g_gp[MTOK * DMODEL];
__device__ float g_o [MTOK * DMODEL];
__device__ float g_t16[MTOK * 16];

__device__ __nv_bfloat16 g_xh[MTOK * DMODEL],   g_xl[MTOK * DMODEL];
__device__ __nv_bfloat16 g_zh[MTOK * DMODEL],   g_zl[MTOK * DMODEL];
__device__ __nv_bfloat16 g_wqh[DQK * DMODEL],   g_wql[DQK * DMODEL];
__device__ __nv_bfloat16 g_wkh[DQK * DMODEL],   g_wkl[DQK * DMODEL];
__device__ __nv_bfloat16 g_wvh[DMODEL * DMODEL], g_wvl[DMODEL * DMODEL];
__device__ __nv_bfloat16 g_wgh[DMODEL * DMODEL], g_wgl[DMODEL * DMODEL];
__device__ __nv_bfloat16 g_woh[DMODEL * DMODEL], g_wol[DMODEL * DMODEL];

// ---------------------------------------------------------------------------
// PTX helpers
// ---------------------------------------------------------------------------
__device__ __forceinline__ uint32_t smem_u32(const void* p) {
    uint32_t a;
    asm("{ .reg .u64 t; cvta.to.shared.u64 t, %1; cvt.u32.u64 %0, t; }" : "=r"(a) : "l"(p));
    return a;
}

#define SWZ(o) ((o) ^ (((o) >> 3) & 0x70))

#if USE_TCGEN05
__device__ __forceinline__ uint32_t elect_one_pred() {
    uint32_t pred;
    asm volatile("{\n\t.reg .pred p;\n\telect.sync _|p, 0xFFFFFFFF;\n\t"
                 "selp.b32 %0, 1, 0, p;\n\t}" : "=r"(pred));
    return pred;
}

#define MBARRIER_INIT(mb, cnt) \
    asm volatile("mbarrier.init.shared.b64 [%0], %1;" :: "r"((uint32_t)(mb)), "r"((uint32_t)(cnt)) : "memory")

#define MBARRIER_WAIT_PARITY(mb, par) do { \
    uint32_t _mb = (uint32_t)(mb); uint32_t _p = (uint32_t)(par); uint32_t _done; \
    asm volatile("{\n\t.reg .pred p;\n\t" \
        "mbarrier.try_wait.parity.acquire.cta.shared::cta.b64 p, [%1], %2;\n\t" \
        "selp.b32 %0, 1, 0, p;\n\t}" : "=r"(_done) : "r"(_mb), "r"(_p) : "memory"); \
    if (!_done) { \
        asm volatile("{\n\t.reg .pred P1;\n\t" \
            "WL_%=:\n\t" \
            "mbarrier.try_wait.parity.acquire.cta.shared::cta.b64 P1, [%0], %1, 0x989680;\n\t" \
            "@P1 bra.uni WD_%=;\n\t" \
            "bra.uni WL_%=;\n\t" \
            "WD_%=:\n\t}" :: "r"(_mb), "r"(_p) : "memory"); \
    } \
} while (0)

#define TCGEN05_ALLOC(smem_res, ncols) \
    asm volatile("tcgen05.alloc.cta_group::1.sync.aligned.shared::cta.b32 [%0], %1;" \
                 :: "r"((uint32_t)(smem_res)), "r"((uint32_t)(ncols)) : "memory")
#define TCGEN05_DEALLOC(tm, ncols) \
    asm volatile("tcgen05.dealloc.cta_group::1.sync.aligned.b32 %0, %1;" :: "r"(tm), "r"((uint32_t)(ncols)))
#define TCGEN05_RELINQ() \
    asm volatile("tcgen05.relinquish_alloc_permit.cta_group::1.sync.aligned;")
#define TCGEN05_COMMIT(mb) \
    asm volatile("tcgen05.commit.cta_group::1.mbarrier::arrive::one.shared::cluster.b64 [%0];" \
                 :: "r"((uint32_t)(mb)) : "memory")
#define TCGEN05_FENCE_AFTER() \
    asm volatile("tcgen05.fence::after_thread_sync;" ::: "memory")
#define TCGEN05_WAIT_LD() \
    asm volatile("tcgen05.wait::ld.sync.aligned;" ::: "memory")
#define FENCE_PROXY_ASYNC() \
    asm volatile("fence.proxy.async.shared::cta;" ::: "memory")

#define TCGEN05_LD_X32(r, tm) \
    asm volatile("tcgen05.ld.sync.aligned.32x32b.x32.b32 " \
        "{%0, %1, %2, %3, %4, %5, %6, %7, %8, %9, %10, %11, %12, %13, %14, %15, " \
        " %16, %17, %18, %19, %20, %21, %22, %23, %24, %25, %26, %27, %28, %29, %30, %31}, [%32];" \
        : "=r"((r)[0]),  "=r"((r)[1]),  "=r"((r)[2]),  "=r"((r)[3]), \
          "=r"((r)[4]),  "=r"((r)[5]),  "=r"((r)[6]),  "=r"((r)[7]), \
          "=r"((r)[8]),  "=r"((r)[9]),  "=r"((r)[10]), "=r"((r)[11]), \
          "=r"((r)[12]), "=r"((r)[13]), "=r"((r)[14]), "=r"((r)[15]), \
          "=r"((r)[16]), "=r"((r)[17]), "=r"((r)[18]), "=r"((r)[19]), \
          "=r"((r)[20]), "=r"((r)[21]), "=r"((r)[22]), "=r"((r)[23]), \
          "=r"((r)[24]), "=r"((r)[25]), "=r"((r)[26]), "=r"((r)[27]), \
          "=r"((r)[28]), "=r"((r)[29]), "=r"((r)[30]), "=r"((r)[31]) \
        : "r"(tm))

// K-major SW128 descriptor: layout=2 (SW128), version=1, SBO=64, LBO=1
static constexpr uint64_t DESC_BASE_SW128 =
    (uint64_t(2) << 61) | (uint64_t(1) << 46) | (uint64_t(64) << 32) | (uint64_t(1) << 16);
#define MAKE_DESC(addr) (DESC_BASE_SW128 | ((uint64_t)((addr) >> 4) & 0x3FFF))

__device__ __forceinline__ void mma_f16_ss(uint32_t d, uint64_t ad, uint64_t bd,
                                           uint32_t idesc, uint32_t en) {
    asm volatile("{\n\t.reg .pred p;\n\tsetp.ne.u32 p, %5, 0;\n\t"
        "tcgen05.mma.cta_group::1.kind::f16 [%0], %1, %2, %3, {%4, %4, %4, %4}, p;\n\t}"
        :: "r"(d), "l"(ad), "l"(bd), "r"(idesc), "r"(0u), "r"(en) : "memory");
}
#else
// HMMA fallback primitive: m16n8k16 row.col bf16 -> f32
__device__ __forceinline__ void mma16816(float* d, const uint32_t* a, const uint32_t* b) {
    asm volatile("mma.sync.aligned.m16n8k16.row.col.f32.bf16.bf16.f32 "
        "{%0,%1,%2,%3}, {%4,%5,%6,%7}, {%8,%9}, {%0,%1,%2,%3};"
        : "+f"(d[0]), "+f"(d[1]), "+f"(d[2]), "+f"(d[3])
        : "r"(a[0]), "r"(a[1]), "r"(a[2]), "r"(a[3]), "r"(b[0]), "r"(b[1]));
}
#endif

// ---------------------------------------------------------------------------
// bf16x3 GEMM:  C[M,N] = alpha * (A @ B^T) (+ bias), split hi/lo operands.
// Tile 128x128, K-chunk 64, 256 threads, double-buffered swizzled SMEM.
// sm_103a pass: tcgen05 SS-mode with PER-BUFFER mbarriers (no parity alias).
// Generic pass: mma.sync HMMA.
// ---------------------------------------------------------------------------
#define BUFB 65536
#define GEMM_DSM (2 * BUFB + 1024)

__global__ __launch_bounds__(256) __cluster_dims__(1, 1, 1)
void gemm3(const __nv_bfloat16* __restrict__ Ah, const __nv_bfloat16* __restrict__ Al,
           const __nv_bfloat16* __restrict__ Bh, const __nv_bfloat16* __restrict__ Bl,
           const float* __restrict__ bias, float* __restrict__ C,
           int N, int K, float alpha)
{
    extern __shared__ char dsm[];

    const int tid = threadIdx.x;
    const int bm = blockIdx.y * 128;
    const int bn = blockIdx.x * 128;

    const uint32_t raw = smem_u32(dsm);
    const uint32_t sbase = (raw + 1023u) & ~1023u;
    char* sgen = dsm + (sbase - raw);

    // chunk loader: 4 tiles (Ahi, Alo, Bhi, Blo), each 128 rows x 128B, SW128
    auto load_chunk = [&](int c) {
        char* bb = sgen + (c & 1) * BUFB;
        const int k0 = c * 64;
#pragma unroll
        for (int t4 = 0; t4 < 4; t4++) {
            const __nv_bfloat16* basep = (t4 == 0) ? Ah : (t4 == 1) ? Al : (t4 == 2) ? Bh : Bl;
            const int rowoff = (t4 < 2) ? bm : bn;
            char* tb = bb + t4 * 16384;
#pragma unroll
            for (int ii = 0; ii < 4; ii++) {
                int idx = ii * 256 + tid;     // 0..1023
                int r   = idx >> 3;
                int seg = idx & 7;
                uint4 val = *(const uint4*)(basep + (size_t)(rowoff + r) * K + k0 + seg * 8);
                uint32_t off = (uint32_t)(r * 128 + seg * 16);
                *(uint4*)(tb + SWZ(off)) = val;
            }
        }
    };

    const int NC = K / 64;

#if USE_TCGEN05
    __shared__ uint32_t s_tmem;
    __shared__ __align__(16) uint64_t s_mbar[2];   // one per SMEM buffer
    const uint32_t mbar0 = smem_u32(&s_mbar[0]);
    const uint32_t mbar1 = smem_u32(&s_mbar[1]);

    if (tid < 32) { TCGEN05_ALLOC(smem_u32(&s_tmem), 128); TCGEN05_RELINQ(); }
    if (tid == 0) { MBARRIER_INIT(mbar0, 1); MBARRIER_INIT(mbar1, 1); }

    load_chunk(0);
    FENCE_PROXY_ASYNC();
    __syncthreads();
    const uint32_t tmem = s_tmem;

    const uint32_t IDESC = (1u << 4) | (1u << 7) | (1u << 10) | (16u << 17) | (8u << 24);

    for (int c = 0; c < NC; c++) {
        if (tid < 32 && elect_one_pred()) {
            const uint32_t ab = sbase + (c & 1) * BUFB;
            const uint64_t dAh = MAKE_DESC(ab);
            const uint64_t dAl = MAKE_DESC(ab + 16384);
            const uint64_t dBh = MAKE_DESC(ab + 32768);
            const uint64_t dBl = MAKE_DESC(ab + 49152);
#pragma unroll
            for (int ks = 0; ks < 4; ks++)
                mma_f16_ss(tmem, dAh + ks * 2, dBh + ks * 2, IDESC, (c > 0) || (ks > 0));
#pragma unroll
            for (int ks = 0; ks < 4; ks++)
                mma_f16_ss(tmem, dAh + ks * 2, dBl + ks * 2, IDESC, 1u);
#pragma unroll
            for (int ks = 0; ks < 4; ks++)
                mma_f16_ss(tmem, dAl + ks * 2, dBh + ks * 2, IDESC, 1u);
            TCGEN05_COMMIT((c & 1) ? mbar1 : mbar0);
        }
        if (c + 1 < NC) {
            if (c >= 1) {
                // wait for chunk c-1 (buffer (c+1)&1). Its completion index on
                // mbar[(c-1)&1] is (c-1)>>1 -> parity ((c-1)>>1)&1.
                MBARRIER_WAIT_PARITY(((c - 1) & 1) ? mbar1 : mbar0, ((c - 1) >> 1) & 1);
            }
            load_chunk(c + 1);
            FENCE_PROXY_ASYNC();
            __syncthreads();
        }
    }
    // chunks complete in issue order: waiting for the last one covers all.
    MBARRIER_WAIT_PARITY(((NC - 1) & 1) ? mbar1 : mbar0, ((NC - 1) >> 1) & 1);
    TCGEN05_FENCE_AFTER();

    // epilogue: TMEM -> regs -> padded SMEM stage -> coalesced STG
    float* stage = (float*)sgen;
    for (int slab = 0; slab < 4; slab++) {
        if (tid < 128) {
            uint32_t regs[32];
            TCGEN05_LD_X32(regs, tmem + slab * 32);
            TCGEN05_WAIT_LD();
#pragma unroll
            for (int cc = 0; cc < 32; cc++) stage[tid * 33 + cc] = __uint_as_float(regs[cc]);
        }
        __syncthreads();
#pragma unroll
        for (int i = 0; i < 16; i++) {
            int e = i * 256 + tid;
            int row = e >> 5, col = e & 31;
            float vv = stage[row * 33 + col] * alpha;
            if (bias) vv += bias[bn + slab * 32 + col];
            C[(size_t)(bm + row) * N + bn + slab * 32 + col] = vv;
        }
        __syncthreads();
    }
    if (tid < 32) TCGEN05_DEALLOC(tmem, 128);

#else  // ------------------- HMMA mma.sync fallback ------------------------
    const int warp = tid >> 5;
    const int lane = tid & 31;
    const int wm = (warp & 3) * 32;     // warp tile 32 x 64
    const int wn = (warp >> 2) * 64;
    const int lg = lane >> 2;           // 0..7
    const int lt = lane & 3;            // 0..3

    float acc[2][8][4];
#pragma unroll
    for (int mt = 0; mt < 2; mt++)
#pragma unroll
        for (int nt = 0; nt < 8; nt++)
#pragma unroll
            for (int r = 0; r < 4; r++) acc[mt][nt][r] = 0.f;

    load_chunk(0);
    __syncthreads();

    for (int c = 0; c < NC; c++) {
        char* bb = sgen + (c & 1) * BUFB;
        char* tAh = bb, *tAl = bb + 16384, *tBh = bb + 32768, *tBl = bb + 49152;

#pragma unroll
        for (int kk = 0; kk < 64; kk += 16) {
            const uint32_t kbase = (kk + lt * 2) * 2;   // byte offset of k-pair
            uint32_t bh[8][2], bl[8][2];
#pragma unroll
            for (int nt = 0; nt < 8; nt++) {
                uint32_t off = (uint32_t)((wn + nt * 8 + lg) * 128) + kbase;
                bh[nt][0] = *(const uint32_t*)(tBh + SWZ(off));
                bh[nt][1] = *(const uint32_t*)(tBh + SWZ(off + 16));
                bl[nt][0] = *(const uint32_t*)(tBl + SWZ(off));
                bl[nt][1] = *(const uint32_t*)(tBl + SWZ(off + 16));
            }
#pragma unroll
            for (int mt = 0; mt < 2; mt++) {
                uint32_t o0 = (uint32_t)((wm + mt * 16 + lg) * 128) + kbase;
                uint32_t o8 = o0 + 8 * 128;
                uint32_t ah[4] = {
                    *(const uint32_t*)(tAh + SWZ(o0)),      *(const uint32_t*)(tAh + SWZ(o8)),
                    *(const uint32_t*)(tAh + SWZ(o0 + 16)), *(const uint32_t*)(tAh + SWZ(o8 + 16)) };
                uint32_t al[4] = {
                    *(const uint32_t*)(tAl + SWZ(o0)),      *(const uint32_t*)(tAl + SWZ(o8)),
                    *(const uint32_t*)(tAl + SWZ(o0 + 16)), *(const uint32_t*)(tAl + SWZ(o8 + 16)) };
#pragma unroll
                for (int nt = 0; nt < 8; nt++) mma16816(acc[mt][nt], ah, bh[nt]);
#pragma unroll
                for (int nt = 0; nt < 8; nt++) mma16816(acc[mt][nt], ah, bl[nt]);
#pragma unroll
                for (int nt = 0; nt < 8; nt++) mma16816(acc[mt][nt], al, bh[nt]);
            }
        }
        __syncthreads();
        if (c + 1 < NC) { load_chunk(c + 1); __syncthreads(); }
    }

    // epilogue: direct float2 stores
#pragma unroll
    for (int mt = 0; mt < 2; mt++) {
#pragma unroll
        for (int nt = 0; nt < 8; nt++) {
            int row = bm + wm + mt * 16 + lg;
            int col = bn + wn + nt * 8 + lt * 2;
            float b0 = bias ? bias[col]     : 0.f;
            float b1 = bias ? bias[col + 1] : 0.f;
            float2 v0 = { acc[mt][nt][0] * alpha + b0, acc[mt][nt][1] * alpha + b1 };
            float2 v1 = { acc[mt][nt][2] * alpha + b0, acc[mt][nt][3] * alpha + b1 };
            *(float2*)(C + (size_t)row * N + col)       = v0;
            *(float2*)(C + (size_t)(row + 8) * N + col) = v1;
        }
    }
#endif
}

// ---------------------------------------------------------------------------
// fp32 -> (hi, lo) bf16 split, vectorized by 4
// ---------------------------------------------------------------------------
__global__ __launch_bounds__(256)
void split32(const float* __restrict__ s, __nv_bfloat16* __restrict__ hi,
             __nv_bfloat16* __restrict__ lo, int n4)
{
    int i = blockIdx.x * blockDim.x + threadIdx.x;
    if (i >= n4) return;
    float4 v = ((const float4*)s)[i];
    __nv_bfloat16 h0 = __float2bfloat16(v.x), h1 = __float2bfloat16(v.y);
    __nv_bfloat16 h2 = __float2bfloat16(v.z), h3 = __float2bfloat16(v.w);
    __nv_bfloat16 l0 = __float2bfloat16(v.x - __bfloat162float(h0));
    __nv_bfloat16 l1 = __float2bfloat16(v.y - __bfloat162float(h1));
    __nv_bfloat16 l2 = __float2bfloat16(v.z - __bfloat162float(h2));
    __nv_bfloat16 l3 = __float2bfloat16(v.w - __bfloat162float(h3));
    ushort4 ph = { __bfloat16_as_ushort(h0), __bfloat16_as_ushort(h1),
                   __bfloat16_as_ushort(h2), __bfloat16_as_ushort(h3) };
    ushort4 pl = { __bfloat16_as_ushort(l0), __bfloat16_as_ushort(l1),
                   __bfloat16_as_ushort(l2), __bfloat16_as_ushort(l3) };
    ((ushort4*)hi)[i] = ph;
    ((ushort4*)lo)[i] = pl;
}

// ---------------------------------------------------------------------------
// Low-rank gate (fp32 SIMT — tiny)
// ---------------------------------------------------------------------------
__global__ void kg_gemm1(const float* __restrict__ x, const float* __restrict__ W,
                         float* __restrict__ t16)
{
    int idx = blockIdx.x * blockDim.x + threadIdx.x;   // 4096*16
    int m = idx >> 4, n = idx & 15;
    const float* xr = x + (size_t)m * DMODEL;
    const float* wr = W + (size_t)n * DMODEL;
    float acc = 0.f;
#pragma unroll 4
    for (int kk = 0; kk < DMODEL; kk += 4) {
        float4 a = *(const float4*)(xr + kk);
        float4 b = *(const float4*)(wr + kk);
        acc += a.x * b.x + a.y * b.y + a.z * b.z + a.w * b.w;
    }
    t16[idx] = acc;
}

__global__ void kg_gemm2(const float* __restrict__ t16, const float* __restrict__ W2,
                         const float* __restrict__ b2, float* __restrict__ kg)
{
    int idx = blockIdx.x * blockDim.x + threadIdx.x;   // 4096*1024
    int m = idx >> 10, n = idx & 1023;
    const float* tr = t16 + (size_t)m * 16;
    const float* wr = W2 + (size_t)n * 16;
    float acc = b2[n];
#pragma unroll
    for (int c = 0; c < 16; c++) acc = fmaf(tr[c], wr[c], acc);
    kg[idx] = acc;
}

// ---------------------------------------------------------------------------
// GLA recurrence. One block per (b, head, dv-chunk of 32).
// ---------------------------------------------------------------------------
#define TT 16
__global__ __launch_bounds__(256)
void gla_rec(const float* __restrict__ q, const float* __restrict__ k,
             const float* __restrict__ kg, const float* __restrict__ v,
             float* __restrict__ o)
{
    const int blk   = blockIdx.x;       // 128 = B * H * 4
    const int chunk = blk & 3;
    const int head  = (blk >> 2) & 15;
    const int b     = blk >> 6;
    const int j0    = chunk * 32;

    const int tid = threadIdx.x;
    const int j   = tid >> 3;           // 0..31
    const int ig  = tid & 7;            // 0..7

    __shared__ float qs[TT][DK];
    __shared__ float ks[TT][DK];
    __shared__ float es[TT][DK];
    __shared__ float vs[TT][32];

    const float* qb = q  + (size_t)b * SEQ * DQK    + head * DK;
    const float* kb = k  + (size_t)b * SEQ * DQK    + head * DK;
    const float* gb = kg + (size_t)b * SEQ * DQK    + head * DK;
    const float* vb = v  + (size_t)b * SEQ * DMODEL + head * DV + j0;
    float*       ob = o  + (size_t)b * SEQ * DMODEL + head * DV + j0;

    float S[8] = {0.f, 0.f, 0.f, 0.f, 0.f, 0.f, 0.f, 0.f};

    for (int t0 = 0; t0 < SEQ; t0 += TT) {
        for (int idx = tid; idx < TT * DK; idx += 256) {
            int tt = idx >> 6, i = idx & 63;
            size_t off = (size_t)(t0 + tt) * DQK + i;
            qs[tt][i] = qb[off];
            ks[tt][i] = kb[off];
            float xg = gb[off];
            float ls = (xg >= 0.f) ? -log1pf(expf(-xg)) : (xg - log1pf(expf(xg)));
            es[tt][i] = expf(ls * INV_NORM);
        }
        for (int idx = tid; idx < TT * 32; idx += 256) {
            int tt = idx >> 5, jj = idx & 31;
            vs[tt][jj] = vb[(size_t)(t0 + tt) * DMODEL + jj];
        }
        __syncthreads();

        for (int tt = 0; tt < TT; tt++) {
            float vj  = vs[tt][j];
            float acc = 0.f;
#pragma unroll
            for (int r = 0; r < 8; r++) {
                int i = ig * 8 + r;
                float s = fmaf(S[r], es[tt][i], ks[tt][i] * vj);
                S[r] = s;
                acc = fmaf(qs[tt][i], s, acc);
            }
            acc += __shfl_xor_sync(0xffffffffu, acc, 4);
            acc += __shfl_xor_sync(0xffffffffu, acc, 2);
            acc += __shfl_xor_sync(0xffffffffu, acc, 1);
            if (ig == 0) ob[(size_t)(t0 + tt) * DMODEL + j] = acc;
        }
        __syncthreads();
    }
}

// ---------------------------------------------------------------------------
// LayerNorm(dv=128, no affine) + SiLU gate, fused hi/lo bf16 split of z
// ---------------------------------------------------------------------------
__global__ __launch_bounds__(256)
void ln_gate(const float* __restrict__ o, const float* __restrict__ gp,
             __nv_bfloat16* __restrict__ zh, __nv_bfloat16* __restrict__ zl)
{
    int gw   = (blockIdx.x * blockDim.x + threadIdx.x) >> 5;   // row id, 65536 total
    int lane = threadIdx.x & 31;

    float4 ov = ((const float4*)(o + (size_t)gw * 128))[lane];
    float s = ov.x + ov.y + ov.z + ov.w;
#pragma unroll
    for (int d = 16; d > 0; d >>= 1) s += __shfl_xor_sync(0xffffffffu, s, d);
    float mu = s * (1.f / 128.f);

    float dx0 = ov.x - mu, dx1 = ov.y - mu, dx2 = ov.z - mu, dx3 = ov.w - mu;
    float vsum = dx0 * dx0 + dx1 * dx1 + dx2 * dx2 + dx3 * dx3;
#pragma unroll
    for (int d = 16; d > 0; d >>= 1) vsum += __shfl_xor_sync(0xffffffffu, vsum, d);
    float inv = rsqrtf(vsum * (1.f / 128.f) + 1e-5f);

    float4 gv = ((const float4*)(gp + (size_t)gw * 128))[lane];
    float z0 = (gv.x / (1.f + expf(-gv.x))) * (dx0 * inv);
    float z1 = (gv.y / (1.f + expf(-gv.y))) * (dx1 * inv);
    float z2 = (gv.z / (1.f + expf(-gv.z))) * (dx2 * inv);
    float z3 = (gv.w / (1.f + expf(-gv.w))) * (dx3 * inv);

    __nv_bfloat16 h0 = __float2bfloat16(z0), h1 = __float2bfloat16(z1);
    __nv_bfloat16 h2 = __float2bfloat16(z2), h3 = __float2bfloat16(z3);
    __nv_bfloat16 l0 = __float2bfloat16(z0 - __bfloat162float(h0));
    __nv_bfloat16 l1 = __float2bfloat16(z1 - __bfloat162float(h1));
    __nv_bfloat16 l2 = __float2bfloat16(z2 - __bfloat162float(h2));
    __nv_bfloat16 l3 = __float2bfloat16(z3 - __bfloat162float(h3));
    ushort4 ph = { __bfloat16_as_ushort(h0), __bfloat16_as_ushort(h1),
                   __bfloat16_as_ushort(h2), __bfloat16_as_ushort(h3) };
    ushort4 pl = { __bfloat16_as_ushort(l0), __bfloat16_as_ushort(l1),
                   __bfloat16_as_ushort(l2), __bfloat16_as_ushort(l3) };
    ((ushort4*)zh)[gw * 32 + lane] = ph;
    ((ushort4*)zl)[gw * 32 + lane] = pl;
}

// ---------------------------------------------------------------------------
extern "C" void kernel_launch(void* const* d_in, const int* in_sizes, int n_in,
                              void* d_out, int out_size)
{
    const float* x    = (const float*)d_in[0];
    const float* Wq   = (const float*)d_in[1];
    const float* Wk   = (const float*)d_in[2];
    const float* Wkg1 = (const float*)d_in[3];
    const float* Wkg2 = (const float*)d_in[4];
    const float* bkg2 = (const float*)d_in[5];
    const float* Wv   = (const float*)d_in[6];
    const float* Wg   = (const float*)d_in[7];
    const float* bg   = (const float*)d_in[8];
    const float* Wo   = (const float*)d_in[9];
    float* out = (float*)d_out;

    float *q, *k, *kg, *v, *gp, *o, *t16;
    cudaGetSymbolAddress((void**)&q,   g_q);
    cudaGetSymbolAddress((void**)&k,   g_k);
    cudaGetSymbolAddress((void**)&kg,  g_kg);
    cudaGetSymbolAddress((void**)&v,   g_v);
    cudaGetSymbolAddress((void**)&gp,  g_gp);
    cudaGetSymbolAddress((void**)&o,   g_o);
    cudaGetSymbolAddress((void**)&t16, g_t16);

    __nv_bfloat16 *xh, *xl, *zh, *zl;
    __nv_bfloat16 *wqh, *wql, *wkh, *wkl, *wvh, *wvl, *wgh, *wgl, *woh, *wol;
    cudaGetSymbolAddress((void**)&xh,  g_xh);  cudaGetSymbolAddress((void**)&xl,  g_xl);
    cudaGetSymbolAddress((void**)&zh,  g_zh);  cudaGetSymbolAddress((void**)&zl,  g_zl);
    cudaGetSymbolAddress((void**)&wqh, g_wqh); cudaGetSymbolAddress((void**)&wql, g_wql);
    cudaGetSymbolAddress((void**)&wkh, g_wkh); cudaGetSymbolAddress((void**)&wkl, g_wkl);
    cudaGetSymbolAddress((void**)&wvh, g_wvh); cudaGetSymbolAddress((void**)&wvl, g_wvl);
    cudaGetSymbolAddress((void**)&wgh, g_wgh); cudaGetSymbolAddress((void**)&wgl, g_wgl);
    cudaGetSymbolAddress((void**)&woh, g_woh); cudaGetSymbolAddress((void**)&wol, g_wol);

    cudaFuncSetAttribute(gemm3, cudaFuncAttributeMaxDynamicSharedMemorySize, GEMM_DSM);

    // hi/lo splits
    int n4x = (MTOK * DMODEL) / 4;
    int n4w1 = (DQK * DMODEL) / 4;
    int n4w2 = (DMODEL * DMODEL) / 4;
    split32<<<n4x / 256, 256>>>(x, xh, xl, n4x);
    split32<<<n4w1 / 256, 256>>>(Wq, wqh, wql, n4w1);
    split32<<<n4w1 / 256, 256>>>(Wk, wkh, wkl, n4w1);
    split32<<<n4w2 / 256, 256>>>(Wv, wvh, wvl, n4w2);
    split32<<<n4w2 / 256, 256>>>(Wg, wgh, wgl, n4w2);
    split32<<<n4w2 / 256, 256>>>(Wo, woh, wol, n4w2);

    dim3 blk(256);
    dim3 gQK(DQK / 128, MTOK / 128);      // 8 x 32
    dim3 gD (DMODEL / 128, MTOK / 128);   // 16 x 32

    gemm3<<<gQK, blk, GEMM_DSM>>>(xh, xl, wqh, wql, nullptr, q,  DQK,    DMODEL, 1.f);
    gemm3<<<gQK, blk, GEMM_DSM>>>(xh, xl, wkh, wkl, nullptr, k,  DQK,    DMODEL, SCALE_K);
    gemm3<<<gD,  blk, GEMM_DSM>>>(xh, xl, wvh, wvl, nullptr, v,  DMODEL, DMODEL, 1.f);
    gemm3<<<gD,  blk, GEMM_DSM>>>(xh, xl, wgh, wgl, bg,      gp, DMODEL, DMODEL, 1.f);

    kg_gemm1<<<(MTOK * 16) / 256, 256>>>(x, Wkg1, t16);
    kg_gemm2<<<(MTOK * DQK) / 256, 256>>>(t16, Wkg2, bkg2, kg);

    gla_rec<<<128, 256>>>(q, k, kg, v, o);

    ln_gate<<<(MTOK * NHEAD * 32) / 256, 256>>>(o, gp, zh, zl);

    gemm3<<<gD, blk, GEMM_DSM>>>(zh, zl, woh, wol, nullptr, out, DMODEL, DMODEL, 1.f);
}

// round 5
// speedup vs baseline: 5.1126x; 1.5553x over previous
#include <cuda_runtime.h>
#include <cuda_bf16.h>
#include <math.h>
#include <cstdint>

// ---------------------------------------------------------------------------
// Problem constants: B=2, L=2048, D=2048, H=16, dk=64, dv=128.  M = B*L = 4096.
// ---------------------------------------------------------------------------
#define MTOK 4096
#define DMODEL 2048
#define DQK 1024
#define NHEAD 16
#define DK 64
#define DV 128
#define SEQ 2048
#define SCALE_K 0.08838834764831845f   // 128^-0.5
#define INV_NORM 0.0625f               // 1/16

// tcgen05 only exists in the arch-specific (sm_103a) compilation pass.
#if defined(__CUDA_ARCH__) && (__CUDA_ARCH__ == 1030) && defined(__CUDA_ARCH_FEAT_SM103_ALL)
#define USE_TCGEN05 1
#else
#define USE_TCGEN05 0
#endif

// ---------------------------------------------------------------------------
// Scratch (device globals: no allocation allowed)
// ---------------------------------------------------------------------------
__device__ float g_q [MTOK * DQK];
__device__ float g_k [MTOK * DQK];
__device__ float g_kg[MTOK * DQK];
__device__ float g_v [MTOK * DMODEL];
__device__ float g_gp[MTOK * DMODEL];
__device__ float g_o [MTOK * DMODEL];
__device__ float g_t16[MTOK * 16];

__device__ __nv_bfloat16 g_xh[MTOK * DMODEL],   g_xl[MTOK * DMODEL];
__device__ __nv_bfloat16 g_zh[MTOK * DMODEL],   g_zl[MTOK * DMODEL];
__device__ __nv_bfloat16 g_wqh[DQK * DMODEL],   g_wql[DQK * DMODEL];
__device__ __nv_bfloat16 g_wkh[DQK * DMODEL],   g_wkl[DQK * DMODEL];
__device__ __nv_bfloat16 g_wvh[DMODEL * DMODEL], g_wvl[DMODEL * DMODEL];
__device__ __nv_bfloat16 g_wgh[DMODEL * DMODEL], g_wgl[DMODEL * DMODEL];
__device__ __nv_bfloat16 g_woh[DMODEL * DMODEL], g_wol[DMODEL * DMODEL];

// ---------------------------------------------------------------------------
// PTX helpers
// ---------------------------------------------------------------------------
__device__ __forceinline__ uint32_t smem_u32(const void* p) {
    uint32_t a;
    asm("{ .reg .u64 t; cvta.to.shared.u64 t, %1; cvt.u32.u64 %0, t; }" : "=r"(a) : "l"(p));
    return a;
}

#define SWZ(o) ((o) ^ (((o) >> 3) & 0x70))

#define CP_ASYNC16(dst, src) \
    asm volatile("cp.async.cg.shared.global [%0], [%1], 16;" :: "r"(dst), "l"(src))
#define CP_ASYNC_COMMIT() \
    asm volatile("cp.async.commit_group;" ::: "memory")
#define CP_ASYNC_WAIT(n) \
    asm volatile("cp.async.wait_group %0;" :: "n"(n) : "memory")

#if USE_TCGEN05
__device__ __forceinline__ uint32_t elect_one_pred() {
    uint32_t pred;
    asm volatile("{\n\t.reg .pred p;\n\telect.sync _|p, 0xFFFFFFFF;\n\t"
                 "selp.b32 %0, 1, 0, p;\n\t}" : "=r"(pred));
    return pred;
}

#define MBARRIER_INIT(mb, cnt) \
    asm volatile("mbarrier.init.shared.b64 [%0], %1;" :: "r"((uint32_t)(mb)), "r"((uint32_t)(cnt)) : "memory")

#define MBARRIER_WAIT_PARITY(mb, par) do { \
    uint32_t _mb = (uint32_t)(mb); uint32_t _p = (uint32_t)(par); uint32_t _done; \
    asm volatile("{\n\t.reg .pred p;\n\t" \
        "mbarrier.try_wait.parity.acquire.cta.shared::cta.b64 p, [%1], %2;\n\t" \
        "selp.b32 %0, 1, 0, p;\n\t}" : "=r"(_done) : "r"(_mb), "r"(_p) : "memory"); \
    if (!_done) { \
        asm volatile("{\n\t.reg .pred P1;\n\t" \
            "WL_%=:\n\t" \
            "mbarrier.try_wait.parity.acquire.cta.shared::cta.b64 P1, [%0], %1, 0x989680;\n\t" \
            "@P1 bra.uni WD_%=;\n\t" \
            "bra.uni WL_%=;\n\t" \
            "WD_%=:\n\t}" :: "r"(_mb), "r"(_p) : "memory"); \
    } \
} while (0)

#define TCGEN05_ALLOC(smem_res, ncols) \
    asm volatile("tcgen05.alloc.cta_group::1.sync.aligned.shared::cta.b32 [%0], %1;" \
                 :: "r"((uint32_t)(smem_res)), "r"((uint32_t)(ncols)) : "memory")
#define TCGEN05_DEALLOC(tm, ncols) \
    asm volatile("tcgen05.dealloc.cta_group::1.sync.aligned.b32 %0, %1;" :: "r"(tm), "r"((uint32_t)(ncols)))
#define TCGEN05_RELINQ() \
    asm volatile("tcgen05.relinquish_alloc_permit.cta_group::1.sync.aligned;")
#define TCGEN05_COMMIT(mb) \
    asm volatile("tcgen05.commit.cta_group::1.mbarrier::arrive::one.shared::cluster.b64 [%0];" \
                 :: "r"((uint32_t)(mb)) : "memory")
#define TCGEN05_FENCE_AFTER() \
    asm volatile("tcgen05.fence::after_thread_sync;" ::: "memory")
#define TCGEN05_WAIT_LD() \
    asm volatile("tcgen05.wait::ld.sync.aligned;" ::: "memory")
#define FENCE_PROXY_ASYNC() \
    asm volatile("fence.proxy.async.shared::cta;" ::: "memory")

#define TCGEN05_LD_X32(r, tm) \
    asm volatile("tcgen05.ld.sync.aligned.32x32b.x32.b32 " \
        "{%0, %1, %2, %3, %4, %5, %6, %7, %8, %9, %10, %11, %12, %13, %14, %15, " \
        " %16, %17, %18, %19, %20, %21, %22, %23, %24, %25, %26, %27, %28, %29, %30, %31}, [%32];" \
        : "=r"((r)[0]),  "=r"((r)[1]),  "=r"((r)[2]),  "=r"((r)[3]), \
          "=r"((r)[4]),  "=r"((r)[5]),  "=r"((r)[6]),  "=r"((r)[7]), \
          "=r"((r)[8]),  "=r"((r)[9]),  "=r"((r)[10]), "=r"((r)[11]), \
          "=r"((r)[12]), "=r"((r)[13]), "=r"((r)[14]), "=r"((r)[15]), \
          "=r"((r)[16]), "=r"((r)[17]), "=r"((r)[18]), "=r"((r)[19]), \
          "=r"((r)[20]), "=r"((r)[21]), "=r"((r)[22]), "=r"((r)[23]), \
          "=r"((r)[24]), "=r"((r)[25]), "=r"((r)[26]), "=r"((r)[27]), \
          "=r"((r)[28]), "=r"((r)[29]), "=r"((r)[30]), "=r"((r)[31]) \
        : "r"(tm))

// K-major SW128 descriptor: layout=2 (SW128), version=1, SBO=64, LBO=1
static constexpr uint64_t DESC_BASE_SW128 =
    (uint64_t(2) << 61) | (uint64_t(1) << 46) | (uint64_t(64) << 32) | (uint64_t(1) << 16);
#define MAKE_DESC(addr) (DESC_BASE_SW128 | ((uint64_t)((addr) >> 4) & 0x3FFF))

__device__ __forceinline__ void mma_f16_ss(uint32_t d, uint64_t ad, uint64_t bd,
                                           uint32_t idesc, uint32_t en) {
    asm volatile("{\n\t.reg .pred p;\n\tsetp.ne.u32 p, %5, 0;\n\t"
        "tcgen05.mma.cta_group::1.kind::f16 [%0], %1, %2, %3, {%4, %4, %4, %4}, p;\n\t}"
        :: "r"(d), "l"(ad), "l"(bd), "r"(idesc), "r"(0u), "r"(en) : "memory");
}
#else
// HMMA fallback primitive: m16n8k16 row.col bf16 -> f32
__device__ __forceinline__ void mma16816(float* d, const uint32_t* a, const uint32_t* b) {
    asm volatile("mma.sync.aligned.m16n8k16.row.col.f32.bf16.bf16.f32 "
        "{%0,%1,%2,%3}, {%4,%5,%6,%7}, {%8,%9}, {%0,%1,%2,%3};"
        : "+f"(d[0]), "+f"(d[1]), "+f"(d[2]), "+f"(d[3])
        : "r"(a[0]), "r"(a[1]), "r"(a[2]), "r"(a[3]), "r"(b[0]), "r"(b[1]));
}
#endif

// ---------------------------------------------------------------------------
// bf16x3 GEMM:  C[M,N] = alpha * (A @ B^T) (+ bias), split hi/lo operands.
// Tile 128x128, K-chunk 64, 256 threads, double-buffered swizzled SMEM,
// cp.async (LDGSTS) loads with commit/wait groups for load/MMA overlap.
// ---------------------------------------------------------------------------
#define BUFB 65536
#define GEMM_DSM (2 * BUFB + 1024)

__global__ __launch_bounds__(256) __cluster_dims__(1, 1, 1)
void gemm3(const __nv_bfloat16* __restrict__ Ah, const __nv_bfloat16* __restrict__ Al,
           const __nv_bfloat16* __restrict__ Bh, const __nv_bfloat16* __restrict__ Bl,
           const float* __restrict__ bias, float* __restrict__ C,
           int N, int K, float alpha)
{
    extern __shared__ char dsm[];

    const int tid = threadIdx.x;
    const int bm = blockIdx.y * 128;
    const int bn = blockIdx.x * 128;

    const uint32_t raw = smem_u32(dsm);
    const uint32_t sbase = (raw + 1023u) & ~1023u;
    char* sgen = dsm + (sbase - raw);

    // async chunk loader: 4 tiles (Ahi, Alo, Bhi, Blo), 128 rows x 128B, SW128
    const int lr  = tid >> 3;          // 0..31 base row (stride 32)
    const int seg = tid & 7;           // 16B segment within 128B row
    auto load_chunk = [&](int c) {
        uint32_t bb = sbase + (c & 1) * BUFB;
        const int k0 = c * 64;
#pragma unroll
        for (int t4 = 0; t4 < 4; t4++) {
            const __nv_bfloat16* basep = (t4 == 0) ? Ah : (t4 == 1) ? Al : (t4 == 2) ? Bh : Bl;
            const int rowoff = (t4 < 2) ? bm : bn;
            uint32_t tb = bb + t4 * 16384;
#pragma unroll
            for (int ii = 0; ii < 4; ii++) {
                int r = lr + ii * 32;
                const void* src = basep + (size_t)(rowoff + r) * K + k0 + seg * 8;
                uint32_t off = (uint32_t)(r * 128 + seg * 16);
                CP_ASYNC16(tb + SWZ(off), src);
            }
        }
        CP_ASYNC_COMMIT();
    };

    const int NC = K / 64;

#if USE_TCGEN05
    __shared__ uint32_t s_tmem;
    __shared__ __align__(16) uint64_t s_mbar[2];   // one per SMEM buffer
    const uint32_t mbar0 = smem_u32(&s_mbar[0]);
    const uint32_t mbar1 = smem_u32(&s_mbar[1]);

    if (tid < 32) { TCGEN05_ALLOC(smem_u32(&s_tmem), 128); TCGEN05_RELINQ(); }
    if (tid == 0) { MBARRIER_INIT(mbar0, 1); MBARRIER_INIT(mbar1, 1); }
    __syncthreads();
    const uint32_t tmem = s_tmem;

    const uint32_t IDESC = (1u << 4) | (1u << 7) | (1u << 10) | (16u << 17) | (8u << 24);

    load_chunk(0);

    for (int c = 0; c < NC; c++) {
        if (c + 1 < NC) {
            if (c >= 1) {
                // buffer (c+1)&1 was used by MMA chunk c-1; wait for it.
                // chunk c-1 is completion #((c-1)>>1) on mbar[(c-1)&1].
                MBARRIER_WAIT_PARITY(((c - 1) & 1) ? mbar1 : mbar0, ((c - 1) >> 1) & 1);
            }
            load_chunk(c + 1);
            CP_ASYNC_WAIT(1);          // chunk c's group complete (c+1 in flight)
        } else {
            CP_ASYNC_WAIT(0);
        }
        FENCE_PROXY_ASYNC();
        __syncthreads();

        if (tid < 32 && elect_one_pred()) {
            const uint32_t ab = sbase + (c & 1) * BUFB;
            const uint64_t dAh = MAKE_DESC(ab);
            const uint64_t dAl = MAKE_DESC(ab + 16384);
            const uint64_t dBh = MAKE_DESC(ab + 32768);
            const uint64_t dBl = MAKE_DESC(ab + 49152);
#pragma unroll
            for (int ks = 0; ks < 4; ks++)
                mma_f16_ss(tmem, dAh + ks * 2, dBh + ks * 2, IDESC, (c > 0) || (ks > 0));
#pragma unroll
            for (int ks = 0; ks < 4; ks++)
                mma_f16_ss(tmem, dAh + ks * 2, dBl + ks * 2, IDESC, 1u);
#pragma unroll
            for (int ks = 0; ks < 4; ks++)
                mma_f16_ss(tmem, dAl + ks * 2, dBh + ks * 2, IDESC, 1u);
            TCGEN05_COMMIT((c & 1) ? mbar1 : mbar0);
        }
    }
    MBARRIER_WAIT_PARITY(((NC - 1) & 1) ? mbar1 : mbar0, ((NC - 1) >> 1) & 1);
    TCGEN05_FENCE_AFTER();
    __syncthreads();

    // epilogue: TMEM -> regs -> padded SMEM stage -> coalesced STG
    float* stage = (float*)sgen;
    for (int slab = 0; slab < 4; slab++) {
        if (tid < 128) {
            uint32_t regs[32];
            TCGEN05_LD_X32(regs, tmem + slab * 32);
            TCGEN05_WAIT_LD();
#pragma unroll
            for (int cc = 0; cc < 32; cc++) stage[tid * 33 + cc] = __uint_as_float(regs[cc]);
        }
        __syncthreads();
#pragma unroll
        for (int i = 0; i < 16; i++) {
            int e = i * 256 + tid;
            int row = e >> 5, col = e & 31;
            float vv = stage[row * 33 + col] * alpha;
            if (bias) vv += bias[bn + slab * 32 + col];
            C[(size_t)(bm + row) * N + bn + slab * 32 + col] = vv;
        }
        __syncthreads();
    }
    if (tid < 32) TCGEN05_DEALLOC(tmem, 128);

#else  // ------------------- HMMA mma.sync fallback ------------------------
    const int warp = tid >> 5;
    const int lane = tid & 31;
    const int wm = (warp & 3) * 32;     // warp tile 32 x 64
    const int wn = (warp >> 2) * 64;
    const int lg = lane >> 2;           // 0..7
    const int lt = lane & 3;            // 0..3

    float acc[2][8][4];
#pragma unroll
    for (int mt = 0; mt < 2; mt++)
#pragma unroll
        for (int nt = 0; nt < 8; nt++)
#pragma unroll
            for (int r = 0; r < 4; r++) acc[mt][nt][r] = 0.f;

    load_chunk(0);

    for (int c = 0; c < NC; c++) {
        if (c + 1 < NC) { load_chunk(c + 1); CP_ASYNC_WAIT(1); }
        else            { CP_ASYNC_WAIT(0); }
        __syncthreads();

        char* bb = sgen + (c & 1) * BUFB;
        char* tAh = bb, *tAl = bb + 16384, *tBh = bb + 32768, *tBl = bb + 49152;

#pragma unroll
        for (int kk = 0; kk < 64; kk += 16) {
            const uint32_t kbase = (kk + lt * 2) * 2;   // byte offset of k-pair
            uint32_t bh[8][2], bl[8][2];
#pragma unroll
            for (int nt = 0; nt < 8; nt++) {
                uint32_t off = (uint32_t)((wn + nt * 8 + lg) * 128) + kbase;
                bh[nt][0] = *(const uint32_t*)(tBh + SWZ(off));
                bh[nt][1] = *(const uint32_t*)(tBh + SWZ(off + 16));
                bl[nt][0] = *(const uint32_t*)(tBl + SWZ(off));
                bl[nt][1] = *(const uint32_t*)(tBl + SWZ(off + 16));
            }
#pragma unroll
            for (int mt = 0; mt < 2; mt++) {
                uint32_t o0 = (uint32_t)((wm + mt * 16 + lg) * 128) + kbase;
                uint32_t o8 = o0 + 8 * 128;
                uint32_t ah[4] = {
                    *(const uint32_t*)(tAh + SWZ(o0)),      *(const uint32_t*)(tAh + SWZ(o8)),
                    *(const uint32_t*)(tAh + SWZ(o0 + 16)), *(const uint32_t*)(tAh + SWZ(o8 + 16)) };
                uint32_t al[4] = {
                    *(const uint32_t*)(tAl + SWZ(o0)),      *(const uint32_t*)(tAl + SWZ(o8)),
                    *(const uint32_t*)(tAl + SWZ(o0 + 16)), *(const uint32_t*)(tAl + SWZ(o8 + 16)) };
#pragma unroll
                for (int nt = 0; nt < 8; nt++) mma16816(acc[mt][nt], ah, bh[nt]);
#pragma unroll
                for (int nt = 0; nt < 8; nt++) mma16816(acc[mt][nt], ah, bl[nt]);
#pragma unroll
                for (int nt = 0; nt < 8; nt++) mma16816(acc[mt][nt], al, bh[nt]);
            }
        }
        __syncthreads();
    }

    // epilogue: direct float2 stores
#pragma unroll
    for (int mt = 0; mt < 2; mt++) {
#pragma unroll
        for (int nt = 0; nt < 8; nt++) {
            int row = bm + wm + mt * 16 + lg;
            int col = bn + wn + nt * 8 + lt * 2;
            float b0 = bias ? bias[col]     : 0.f;
            float b1 = bias ? bias[col + 1] : 0.f;
            float2 v0 = { acc[mt][nt][0] * alpha + b0, acc[mt][nt][1] * alpha + b1 };
            float2 v1 = { acc[mt][nt][2] * alpha + b0, acc[mt][nt][3] * alpha + b1 };
            *(float2*)(C + (size_t)row * N + col)       = v0;
            *(float2*)(C + (size_t)(row + 8) * N + col) = v1;
        }
    }
#endif
}

// ---------------------------------------------------------------------------
// fp32 -> (hi, lo) bf16 split, vectorized by 4
// ---------------------------------------------------------------------------
__device__ __forceinline__ void split4(const float4 v,
                                       __nv_bfloat16* hi, __nv_bfloat16* lo, int i)
{
    __nv_bfloat16 h0 = __float2bfloat16(v.x), h1 = __float2bfloat16(v.y);
    __nv_bfloat16 h2 = __float2bfloat16(v.z), h3 = __float2bfloat16(v.w);
    __nv_bfloat16 l0 = __float2bfloat16(v.x - __bfloat162float(h0));
    __nv_bfloat16 l1 = __float2bfloat16(v.y - __bfloat162float(h1));
    __nv_bfloat16 l2 = __float2bfloat16(v.z - __bfloat162float(h2));
    __nv_bfloat16 l3 = __float2bfloat16(v.w - __bfloat162float(h3));
    ushort4 ph = { __bfloat16_as_ushort(h0), __bfloat16_as_ushort(h1),
                   __bfloat16_as_ushort(h2), __bfloat16_as_ushort(h3) };
    ushort4 pl = { __bfloat16_as_ushort(l0), __bfloat16_as_ushort(l1),
                   __bfloat16_as_ushort(l2), __bfloat16_as_ushort(l3) };
    ((ushort4*)hi)[i] = ph;
    ((ushort4*)lo)[i] = pl;
}

__global__ __launch_bounds__(256)
void split32(const float* __restrict__ s, __nv_bfloat16* __restrict__ hi,
             __nv_bfloat16* __restrict__ lo)
{
    int i = blockIdx.x * blockDim.x + threadIdx.x;
    split4(((const float4*)s)[i], hi, lo, i);
}

// One launch splitting all five weight matrices.
// Block ranges (256 float4 per block): Wq 2048, Wk 2048, Wv 4096, Wg 4096, Wo 4096.
__global__ __launch_bounds__(256)
void split_w(const float* __restrict__ Wq, const float* __restrict__ Wk,
             const float* __restrict__ Wv, const float* __restrict__ Wg,
             const float* __restrict__ Wo,
             __nv_bfloat16* __restrict__ wqh, __nv_bfloat16* __restrict__ wql,
             __nv_bfloat16* __restrict__ wkh, __nv_bfloat16* __restrict__ wkl,
             __nv_bfloat16* __restrict__ wvh, __nv_bfloat16* __restrict__ wvl,
             __nv_bfloat16* __restrict__ wgh, __nv_bfloat16* __restrict__ wgl,
             __nv_bfloat16* __restrict__ woh, __nv_bfloat16* __restrict__ wol)
{
    int b = blockIdx.x;
    const float* src; __nv_bfloat16 *hi, *lo;
    if      (b < 2048)  { src = Wq; hi = wqh; lo = wql; }
    else if (b < 4096)  { src = Wk; hi = wkh; lo = wkl; b -= 2048; }
    else if (b < 8192)  { src = Wv; hi = wvh; lo = wvl; b -= 4096; }
    else if (b < 12288) { src = Wg; hi = wgh; lo = wgl; b -= 8192; }
    else                { src = Wo; hi = woh; lo = wol; b -= 12288; }
    int i = b * 256 + threadIdx.x;
    split4(((const float4*)src)[i], hi, lo, i);
}

// ---------------------------------------------------------------------------
// Low-rank gate (fp32 SIMT — tiny)
// ---------------------------------------------------------------------------
__global__ void kg_gemm1(const float* __restrict__ x, const float* __restrict__ W,
                         float* __restrict__ t16)
{
    int idx = blockIdx.x * blockDim.x + threadIdx.x;   // 4096*16
    int m = idx >> 4, n = idx & 15;
    const float* xr = x + (size_t)m * DMODEL;
    const float* wr = W + (size_t)n * DMODEL;
    float acc = 0.f;
#pragma unroll 4
    for (int kk = 0; kk < DMODEL; kk += 4) {
        float4 a = *(const float4*)(xr + kk);
        float4 b = *(const float4*)(wr + kk);
        acc += a.x * b.x + a.y * b.y + a.z * b.z + a.w * b.w;
    }
    t16[idx] = acc;
}

__global__ void kg_gemm2(const float* __restrict__ t16, const float* __restrict__ W2,
                         const float* __restrict__ b2, float* __restrict__ kg)
{
    int idx = blockIdx.x * blockDim.x + threadIdx.x;   // 4096*1024
    int m = idx >> 10, n = idx & 1023;
    const float* tr = t16 + (size_t)m * 16;
    const float* wr = W2 + (size_t)n * 16;
    float acc = b2[n];
#pragma unroll
    for (int c = 0; c < 16; c++) acc = fmaf(tr[c], wr[c], acc);
    kg[idx] = acc;
}

// ---------------------------------------------------------------------------
// GLA recurrence. One block per (b, head, dv-chunk of 32). float4 staged loads.
// ---------------------------------------------------------------------------
#define TT 16
__global__ __launch_bounds__(256)
void gla_rec(const float* __restrict__ q, const float* __restrict__ k,
             const float* __restrict__ kg, const float* __restrict__ v,
             float* __restrict__ o)
{
    const int blk   = blockIdx.x;       // 128 = B * H * 4
    const int chunk = blk & 3;
    const int head  = (blk >> 2) & 15;
    const int b     = blk >> 6;
    const int j0    = chunk * 32;

    const int tid = threadIdx.x;
    const int j   = tid >> 3;           // 0..31
    const int ig  = tid & 7;            // 0..7

    __shared__ __align__(16) float qs[TT][DK];
    __shared__ __align__(16) float ks[TT][DK];
    __shared__ __align__(16) float es[TT][DK];
    __shared__ __align__(16) float vs[TT][32];

    const float* qb = q  + (size_t)b * SEQ * DQK    + head * DK;
    const float* kb = k  + (size_t)b * SEQ * DQK    + head * DK;
    const float* gb = kg + (size_t)b * SEQ * DQK    + head * DK;
    const float* vb = v  + (size_t)b * SEQ * DMODEL + head * DV + j0;
    float*       ob = o  + (size_t)b * SEQ * DMODEL + head * DV + j0;

    // load-phase mapping: 256 threads = 16 rows x 16 float4 (q/k/g);
    // v: 128 threads = 16 rows x 8 float4
    const int ltt = tid >> 4;           // row 0..15
    const int lu  = tid & 15;           // float4 col 0..15
    const int vtt = tid >> 3;           // row (first 128 threads)
    const int vu  = tid & 7;

    float S[8] = {0.f, 0.f, 0.f, 0.f, 0.f, 0.f, 0.f, 0.f};

    for (int t0 = 0; t0 < SEQ; t0 += TT) {
        {
            size_t r4 = (size_t)(t0 + ltt) * (DQK / 4) + lu;
            float4 qv = ((const float4*)qb)[r4];
            float4 kv = ((const float4*)kb)[r4];
            float4 gv = ((const float4*)gb)[r4];
            *(float4*)&qs[ltt][lu * 4] = qv;
            *(float4*)&ks[ltt][lu * 4] = kv;
            float4 ev;
            {
                float a0 = fminf(gv.x, 0.f) - log1pf(__expf(-fabsf(gv.x)));
                float a1 = fminf(gv.y, 0.f) - log1pf(__expf(-fabsf(gv.y)));
                float a2 = fminf(gv.z, 0.f) - log1pf(__expf(-fabsf(gv.z)));
                float a3 = fminf(gv.w, 0.f) - log1pf(__expf(-fabsf(gv.w)));
                ev.x = __expf(a0 * INV_NORM); ev.y = __expf(a1 * INV_NORM);
                ev.z = __expf(a2 * INV_NORM); ev.w = __expf(a3 * INV_NORM);
            }
            *(float4*)&es[ltt][lu * 4] = ev;
            if (tid < 128) {
                float4 vv = ((const float4*)vb)[(size_t)(t0 + vtt) * (DMODEL / 4) + vu];
                *(float4*)&vs[vtt][vu * 4] = vv;
            }
        }
        __syncthreads();

        for (int tt = 0; tt < TT; tt++) {
            float vj  = vs[tt][j];
            float acc = 0.f;
#pragma unroll
            for (int r = 0; r < 8; r++) {
                int i = ig * 8 + r;
                float s = fmaf(S[r], es[tt][i], ks[tt][i] * vj);
                S[r] = s;
                acc = fmaf(qs[tt][i], s, acc);
            }
            acc += __shfl_xor_sync(0xffffffffu, acc, 4);
            acc += __shfl_xor_sync(0xffffffffu, acc, 2);
            acc += __shfl_xor_sync(0xffffffffu, acc, 1);
            if (ig == 0) ob[(size_t)(t0 + tt) * DMODEL + j] = acc;
        }
        __syncthreads();
    }
}

// ---------------------------------------------------------------------------
// LayerNorm(dv=128, no affine) + SiLU gate, fused hi/lo bf16 split of z
// ---------------------------------------------------------------------------
__global__ __launch_bounds__(256)
void ln_gate(const float* __restrict__ o, const float* __restrict__ gp,
             __nv_bfloat16* __restrict__ zh, __nv_bfloat16* __restrict__ zl)
{
    int gw   = (blockIdx.x * blockDim.x + threadIdx.x) >> 5;   // row id, 65536 total
    int lane = threadIdx.x & 31;

    float4 ov = ((const float4*)(o + (size_t)gw * 128))[lane];
    float s = ov.x + ov.y + ov.z + ov.w;
#pragma unroll
    for (int d = 16; d > 0; d >>= 1) s += __shfl_xor_sync(0xffffffffu, s, d);
    float mu = s * (1.f / 128.f);

    float dx0 = ov.x - mu, dx1 = ov.y - mu, dx2 = ov.z - mu, dx3 = ov.w - mu;
    float vsum = dx0 * dx0 + dx1 * dx1 + dx2 * dx2 + dx3 * dx3;
#pragma unroll
    for (int d = 16; d > 0; d >>= 1) vsum += __shfl_xor_sync(0xffffffffu, vsum, d);
    float inv = rsqrtf(vsum * (1.f / 128.f) + 1e-5f);

    float4 gv = ((const float4*)(gp + (size_t)gw * 128))[lane];
    float4 z;
    z.x = (gv.x / (1.f + __expf(-gv.x))) * (dx0 * inv);
    z.y = (gv.y / (1.f + __expf(-gv.y))) * (dx1 * inv);
    z.z = (gv.z / (1.f + __expf(-gv.z))) * (dx2 * inv);
    z.w = (gv.w / (1.f + __expf(-gv.w))) * (dx3 * inv);
    split4(z, zh, zl, gw * 32 + lane);
}

// ---------------------------------------------------------------------------
extern "C" void kernel_launch(void* const* d_in, const int* in_sizes, int n_in,
                              void* d_out, int out_size)
{
    const float* x    = (const float*)d_in[0];
    const float* Wq   = (const float*)d_in[1];
    const float* Wk   = (const float*)d_in[2];
    const float* Wkg1 = (const float*)d_in[3];
    const float* Wkg2 = (const float*)d_in[4];
    const float* bkg2 = (const float*)d_in[5];
    const float* Wv   = (const float*)d_in[6];
    const float* Wg   = (const float*)d_in[7];
    const float* bg   = (const float*)d_in[8];
    const float* Wo   = (const float*)d_in[9];
    float* out = (float*)d_out;

    float *q, *k, *kg, *v, *gp, *o, *t16;
    cudaGetSymbolAddress((void**)&q,   g_q);
    cudaGetSymbolAddress((void**)&k,   g_k);
    cudaGetSymbolAddress((void**)&kg,  g_kg);
    cudaGetSymbolAddress((void**)&v,   g_v);
    cudaGetSymbolAddress((void**)&gp,  g_gp);
    cudaGetSymbolAddress((void**)&o,   g_o);
    cudaGetSymbolAddress((void**)&t16, g_t16);

    __nv_bfloat16 *xh, *xl, *zh, *zl;
    __nv_bfloat16 *wqh, *wql, *wkh, *wkl, *wvh, *wvl, *wgh, *wgl, *woh, *wol;
    cudaGetSymbolAddress((void**)&xh,  g_xh);  cudaGetSymbolAddress((void**)&xl,  g_xl);
    cudaGetSymbolAddress((void**)&zh,  g_zh);  cudaGetSymbolAddress((void**)&zl,  g_zl);
    cudaGetSymbolAddress((void**)&wqh, g_wqh); cudaGetSymbolAddress((void**)&wql, g_wql);
    cudaGetSymbolAddress((void**)&wkh, g_wkh); cudaGetSymbolAddress((void**)&wkl, g_wkl);
    cudaGetSymbolAddress((void**)&wvh, g_wvh); cudaGetSymbolAddress((void**)&wvl, g_wvl);
    cudaGetSymbolAddress((void**)&wgh, g_wgh); cudaGetSymbolAddress((void**)&wgl, g_wgl);
    cudaGetSymbolAddress((void**)&woh, g_woh); cudaGetSymbolAddress((void**)&wol, g_wol);

    cudaFuncSetAttribute(gemm3, cudaFuncAttributeMaxDynamicSharedMemorySize, GEMM_DSM);

    // hi/lo splits: 2 launches
    split32<<<(MTOK * DMODEL) / 1024, 256>>>(x, xh, xl);
    split_w<<<16384, 256>>>(Wq, Wk, Wv, Wg, Wo,
                            wqh, wql, wkh, wkl, wvh, wvl, wgh, wgl, woh, wol);

    dim3 blk(256);
    dim3 gQK(DQK / 128, MTOK / 128);      // 8 x 32
    dim3 gD (DMODEL / 128, MTOK / 128);   // 16 x 32

    gemm3<<<gQK, blk, GEMM_DSM>>>(xh, xl, wqh, wql, nullptr, q,  DQK,    DMODEL, 1.f);
    gemm3<<<gQK, blk, GEMM_DSM>>>(xh, xl, wkh, wkl, nullptr, k,  DQK,    DMODEL, SCALE_K);
    gemm3<<<gD,  blk, GEMM_DSM>>>(xh, xl, wvh, wvl, nullptr, v,  DMODEL, DMODEL, 1.f);
    gemm3<<<gD,  blk, GEMM_DSM>>>(xh, xl, wgh, wgl, bg,      gp, DMODEL, DMODEL, 1.f);  // <- ncu -s 5

    kg_gemm1<<<(MTOK * 16) / 256, 256>>>(x, Wkg1, t16);
    kg_gemm2<<<(MTOK * DQK) / 256, 256>>>(t16, Wkg2, bkg2, kg);

    gla_rec<<<128, 256>>>(q, k, kg, v, o);

    ln_gate<<<(MTOK * NHEAD * 32) / 256, 256>>>(o, gp, zh, zl);

    gemm3<<<gD, blk, GEMM_DSM>>>(zh, zl, woh, wol, nullptr, out, DMODEL, DMODEL, 1.f);
}